// round 16
// baseline (speedup 1.0000x reference)
#include <cuda_runtime.h>
#include <cuda_fp16.h>
#include <math.h>
#include <stdint.h>

// Problem shape (fixed by the dataset): N=100000, E=800000, F_IN=96, H=128, C=64.
#define MAXN 100000
#define MAXE 800000
#define FIN 96
#define HID 128
#define COUT 64

// Scratch (static __device__ — no allocations allowed in kernel_launch).
__device__ float4   g_dinv4[(MAXN + 3) / 4];            // d^{-1/2}
__device__ uint2    g_xh2[(size_t)MAXN * FIN / 4];      // x as half [N,96] (4 halves/uint2)
__device__ float4   g_aggx_4[(size_t)MAXN * FIN / 4];   // Â·x  (96-wide, fp32)
__device__ float4   g_h1b_4[(size_t)MAXN * HID / 4];    // relu(aggx@W1+b1)
__device__ uint32_t g_h2h[(size_t)MAXN * COUT / 2];     // h1b@W2 as half (2/uint)
__device__ int      g_src[MAXE];                        // edge src as int32
__device__ int      g_dst[MAXE];                        // edge dst as int32
__device__ int      g_cnt[MAXN];                        // in-degree (no self loop)
__device__ int      g_off[MAXN];                        // row base; after scatter: END
__device__ int2     g_epack[MAXE];                      // CSR slot: (src, dinv[src])
__device__ int      g_total;                            // fused-scan base counter
__device__ unsigned g_anyodd;

#define g_dinv ((float*)g_dinv4)
#define g_aggx ((float*)g_aggx_4)
#define g_h1b  ((float*)g_h1b_4)

// ---------------------------------------------------------------------------
// TF32 helpers
// ---------------------------------------------------------------------------
__device__ __forceinline__ uint32_t f2tf32(float f) {
    uint32_t r;
    asm("cvt.rna.tf32.f32 %0, %1;" : "=r"(r) : "f"(f));
    return r;
}

__device__ __forceinline__ void mma_tf32(float* d, const uint32_t* a,
                                         uint32_t b0, uint32_t b1) {
    asm volatile(
        "mma.sync.aligned.m16n8k8.row.col.f32.tf32.tf32.f32 "
        "{%0,%1,%2,%3}, {%4,%5,%6,%7}, {%8,%9}, {%0,%1,%2,%3};"
        : "+f"(d[0]), "+f"(d[1]), "+f"(d[2]), "+f"(d[3])
        : "r"(a[0]), "r"(a[1]), "r"(a[2]), "r"(a[3]), "r"(b0), "r"(b1));
}

__device__ __forceinline__ uint32_t pack_half2(float a, float b) {
    __half2 h = __floats2half2_rn(a, b);
    return *(uint32_t*)&h;
}

__device__ __forceinline__ float2 unpack_half2(uint32_t u) {
    return __half22float2(*(__half2*)&u);
}

// ---------------------------------------------------------------------------
// Zero degree counters + fused-scan base; one block probes edge-index dtype.
// ---------------------------------------------------------------------------
__global__ void init_detect_kernel(const unsigned* __restrict__ w, int E,
                                   int N) {
    int i = blockIdx.x * blockDim.x + threadIdx.x;
    if (i == 0) { g_anyodd = 0u; g_total = 0; }
    if (i < N) g_cnt[i] = 0;
    if (blockIdx.x == 1) {
        int limit = (E < 4096) ? E : 4096;
        unsigned acc = 0u;
        for (int t = threadIdx.x; t < limit; t += blockDim.x)
            acc |= w[2 * t + 1];
        for (int o = 16; o > 0; o >>= 1)
            acc |= __shfl_xor_sync(0xFFFFFFFFu, acc, o);
        if ((threadIdx.x & 31) == 0 && acc) atomicOr(&g_anyodd, acc);
    }
}

// Convert x[N,96] fp32 -> half copy (gather compression for aggx).
__global__ void x2h_kernel(const float* __restrict__ x, int N) {
    int idx = blockIdx.x * blockDim.x + threadIdx.x;   // over N*24 uint2
    if (idx >= N * 24) return;
    float4 v = ((const float4*)x)[idx];
    uint2 o;
    o.x = pack_half2(v.x, v.y);
    o.y = pack_half2(v.z, v.w);
    g_xh2[idx] = o;
}

// Convert indices to int32 once AND count in-degrees in the same pass.
__global__ void idx_convert_count_kernel(const void* __restrict__ ei, int E) {
    int e = blockIdx.x * blockDim.x + threadIdx.x;
    if (e >= E) return;
    int s, d;
    if (g_anyodd) {          // int32 layout
        const int* p = (const int*)ei;
        s = p[e]; d = p[E + e];
    } else {                 // int64 layout
        const long long* p = (const long long*)ei;
        s = (int)p[e]; d = (int)p[E + e];
    }
    g_src[e] = s;
    g_dst[e] = d;
    atomicAdd(&g_cnt[d], 1);
}

// ---------------------------------------------------------------------------
// Fused single-pass "scan": per-block smem scan + one atomic base claim.
// CSR row order across nodes is irrelevant. Also computes dinv.
// ---------------------------------------------------------------------------
__global__ void scan_fused_kernel(int N) {
    __shared__ int sm[256];
    __shared__ int sbase;
    int i = blockIdx.x * 256 + threadIdx.x;
    int v = (i < N) ? g_cnt[i] : 0;
    sm[threadIdx.x] = v;
    __syncthreads();
#pragma unroll
    for (int o = 1; o < 256; o <<= 1) {
        int t = (threadIdx.x >= o) ? sm[threadIdx.x - o] : 0;
        __syncthreads();
        sm[threadIdx.x] += t;
        __syncthreads();
    }
    if (threadIdx.x == 255) sbase = atomicAdd(&g_total, sm[255]);
    __syncthreads();
    if (i < N) {
        g_off[i] = sbase + sm[threadIdx.x] - v;
        g_dinv[i] = rsqrtf((float)(v + 1));       // +1 = self loop
    }
}

// Scatter edges into CSR slots as packed (src, weight) int2.
__global__ void scatter_kernel(int E) {
    int e = blockIdx.x * blockDim.x + threadIdx.x;
    if (e >= E) return;
    int s = g_src[e], d = g_dst[e];
    int pos = atomicAdd(&g_off[d], 1);
    g_epack[pos] = make_int2(s, __float_as_int(g_dinv[s]));
}

// ---------------------------------------------------------------------------
// Input-space aggregation (CSR, zero atomics): aggx = Â·x  (96-wide).
// Gathers the HALF copy of x (192B/row vs 384B — halves L2 gather traffic).
// One warp per dst; lanes 0..23 each own 4 cols (one uint2 = 4 halves).
// Edge loop unrolled x2 (x4 regressed via L1tex-queue contention, R11/R12).
// ---------------------------------------------------------------------------
__global__ void aggx_csr_kernel(int N) {
    int gid = blockIdx.x * blockDim.x + threadIdx.x;
    int d = gid >> 5;
    int lane = gid & 31;
    if (d >= N || lane >= 24) return;

    int end = g_off[d];
    int beg = end - g_cnt[d];

    float4 acc0 = make_float4(0.f, 0.f, 0.f, 0.f);
    float4 acc1 = make_float4(0.f, 0.f, 0.f, 0.f);
    int j = beg;
    for (; j + 1 < end; j += 2) {
        int2 p0 = g_epack[j], p1 = g_epack[j + 1];
        float w0 = __int_as_float(p0.y);
        float w1 = __int_as_float(p1.y);
        uint2 u0 = g_xh2[(size_t)p0.x * 24 + lane];
        uint2 u1 = g_xh2[(size_t)p1.x * 24 + lane];
        float2 v0a = unpack_half2(u0.x), v0b = unpack_half2(u0.y);
        float2 v1a = unpack_half2(u1.x), v1b = unpack_half2(u1.y);
        acc0.x = fmaf(v0a.x, w0, acc0.x);
        acc0.y = fmaf(v0a.y, w0, acc0.y);
        acc0.z = fmaf(v0b.x, w0, acc0.z);
        acc0.w = fmaf(v0b.y, w0, acc0.w);
        acc1.x = fmaf(v1a.x, w1, acc1.x);
        acc1.y = fmaf(v1a.y, w1, acc1.y);
        acc1.z = fmaf(v1b.x, w1, acc1.z);
        acc1.w = fmaf(v1b.y, w1, acc1.w);
    }
    if (j < end) {
        int2 p0 = g_epack[j];
        float w0 = __int_as_float(p0.y);
        uint2 u0 = g_xh2[(size_t)p0.x * 24 + lane];
        float2 v0a = unpack_half2(u0.x), v0b = unpack_half2(u0.y);
        acc0.x = fmaf(v0a.x, w0, acc0.x);
        acc0.y = fmaf(v0a.y, w0, acc0.y);
        acc0.z = fmaf(v0b.x, w0, acc0.z);
        acc0.w = fmaf(v0b.y, w0, acc0.w);
    }
    acc0.x += acc1.x; acc0.y += acc1.y; acc0.z += acc1.z; acc0.w += acc1.w;

    float dd = g_dinv[d];
    float dd2 = dd * dd;
    uint2 ud = g_xh2[(size_t)d * 24 + lane];
    float2 xda = unpack_half2(ud.x), xdb = unpack_half2(ud.y);
    float4 r;
    r.x = fmaf(acc0.x, dd, xda.x * dd2);
    r.y = fmaf(acc0.y, dd, xda.y * dd2);
    r.z = fmaf(acc0.z, dd, xdb.x * dd2);
    r.w = fmaf(acc0.w, dd, xdb.y * dd2);
    g_aggx_4[(size_t)d * 24 + lane] = r;
}

// ---------------------------------------------------------------------------
// GEMM1 (TF32): h1b[N,128] = relu(aggx[N,96] @ W1[96,128] + b1); also emb.
// ---------------------------------------------------------------------------
__global__ void gemm1_tc_kernel(const float* __restrict__ W1,
                                const float* __restrict__ b1,
                                float* __restrict__ emb, int N) {
    __shared__ __align__(16) uint32_t Xs[128][36];
    __shared__ __align__(16) uint32_t Ws[32][132];
    const int tid = threadIdx.x;
    const int wid = tid >> 5;
    const int lane = tid & 31;
    const int gidl = lane >> 2;
    const int tig = lane & 3;
    const int warp_m = (wid >> 1) * 32;
    const int warp_n = (wid & 1) * 64;
    const int rowBase = blockIdx.x * 128;

    float acc[2][8][4];
#pragma unroll
    for (int mt = 0; mt < 2; mt++)
#pragma unroll
        for (int nt = 0; nt < 8; nt++)
#pragma unroll
            for (int i = 0; i < 4; i++) acc[mt][nt][i] = 0.0f;

    for (int k0 = 0; k0 < FIN; k0 += 32) {
#pragma unroll
        for (int t = tid; t < 1024; t += 256) {
            int r = t >> 3, c = (t & 7) * 4;
            int gr = rowBase + r;
            float4 v = make_float4(0.f, 0.f, 0.f, 0.f);
            if (gr < N) v = *(const float4*)(g_aggx + (size_t)gr * FIN + k0 + c);
            Xs[r][c + 0] = f2tf32(v.x);
            Xs[r][c + 1] = f2tf32(v.y);
            Xs[r][c + 2] = f2tf32(v.z);
            Xs[r][c + 3] = f2tf32(v.w);
        }
#pragma unroll
        for (int t = tid; t < 1024; t += 256) {
            int r = t >> 5, c = (t & 31) * 4;
            float4 v = *(const float4*)(W1 + (size_t)(k0 + r) * HID + c);
            Ws[r][c + 0] = f2tf32(v.x);
            Ws[r][c + 1] = f2tf32(v.y);
            Ws[r][c + 2] = f2tf32(v.z);
            Ws[r][c + 3] = f2tf32(v.w);
        }
        __syncthreads();

#pragma unroll
        for (int kk = 0; kk < 4; kk++) {
            int k8 = kk * 8;
            uint32_t a[2][4];
#pragma unroll
            for (int mt = 0; mt < 2; mt++) {
                int mb = warp_m + mt * 16;
                a[mt][0] = Xs[mb + gidl][k8 + tig];
                a[mt][1] = Xs[mb + gidl + 8][k8 + tig];
                a[mt][2] = Xs[mb + gidl][k8 + tig + 4];
                a[mt][3] = Xs[mb + gidl + 8][k8 + tig + 4];
            }
#pragma unroll
            for (int nt = 0; nt < 8; nt++) {
                int nb = warp_n + nt * 8;
                uint32_t b0 = Ws[k8 + tig][nb + gidl];
                uint32_t b1v = Ws[k8 + tig + 4][nb + gidl];
                mma_tf32(acc[0][nt], a[0], b0, b1v);
                mma_tf32(acc[1][nt], a[1], b0, b1v);
            }
        }
        __syncthreads();
    }

#pragma unroll
    for (int mt = 0; mt < 2; mt++) {
#pragma unroll
        for (int nt = 0; nt < 8; nt++) {
            int col = warp_n + nt * 8 + 2 * tig;
            float2 bb = *(const float2*)(b1 + col);
            int r0 = rowBase + warp_m + mt * 16 + gidl;
            if (r0 < N) {
                float2 v = make_float2(fmaxf(acc[mt][nt][0] + bb.x, 0.f),
                                       fmaxf(acc[mt][nt][1] + bb.y, 0.f));
                *(float2*)(g_h1b + (size_t)r0 * HID + col) = v;
                if (emb) *(float2*)(emb + (size_t)r0 * HID + col) = v;
            }
            if (r0 + 8 < N) {
                float2 v = make_float2(fmaxf(acc[mt][nt][2] + bb.x, 0.f),
                                       fmaxf(acc[mt][nt][3] + bb.y, 0.f));
                *(float2*)(g_h1b + (size_t)(r0 + 8) * HID + col) = v;
                if (emb) *(float2*)(emb + (size_t)(r0 + 8) * HID + col) = v;
            }
        }
    }
}

// ---------------------------------------------------------------------------
// GEMM2 (TF32): h2[N,64] = g_h1b[N,128] @ W2[128,64], stored as HALF
// (128B/row — halves agg2's gather traffic).
// ---------------------------------------------------------------------------
__global__ void gemm2_tc_kernel(const float* __restrict__ W2, int N) {
    __shared__ __align__(16) uint32_t Xs[128][36];
    __shared__ __align__(16) uint32_t Ws[32][68];
    const int tid = threadIdx.x;
    const int wid = tid >> 5;
    const int lane = tid & 31;
    const int gidl = lane >> 2;
    const int tig = lane & 3;
    const int warp_m = wid * 16;
    const int rowBase = blockIdx.x * 128;

    float acc[8][4];
#pragma unroll
    for (int nt = 0; nt < 8; nt++)
#pragma unroll
        for (int i = 0; i < 4; i++) acc[nt][i] = 0.0f;

    for (int k0 = 0; k0 < HID; k0 += 32) {
#pragma unroll
        for (int t = tid; t < 1024; t += 256) {
            int r = t >> 3, c = (t & 7) * 4;
            int gr = rowBase + r;
            float4 v = make_float4(0.f, 0.f, 0.f, 0.f);
            if (gr < N) v = *(const float4*)(g_h1b + (size_t)gr * HID + k0 + c);
            Xs[r][c + 0] = f2tf32(v.x);
            Xs[r][c + 1] = f2tf32(v.y);
            Xs[r][c + 2] = f2tf32(v.z);
            Xs[r][c + 3] = f2tf32(v.w);
        }
#pragma unroll
        for (int t = tid; t < 512; t += 256) {
            int r = t >> 4, c = (t & 15) * 4;
            float4 v = *(const float4*)(W2 + (size_t)(k0 + r) * COUT + c);
            Ws[r][c + 0] = f2tf32(v.x);
            Ws[r][c + 1] = f2tf32(v.y);
            Ws[r][c + 2] = f2tf32(v.z);
            Ws[r][c + 3] = f2tf32(v.w);
        }
        __syncthreads();

#pragma unroll
        for (int kk = 0; kk < 4; kk++) {
            int k8 = kk * 8;
            uint32_t a[4];
            a[0] = Xs[warp_m + gidl][k8 + tig];
            a[1] = Xs[warp_m + gidl + 8][k8 + tig];
            a[2] = Xs[warp_m + gidl][k8 + tig + 4];
            a[3] = Xs[warp_m + gidl + 8][k8 + tig + 4];
#pragma unroll
            for (int nt = 0; nt < 8; nt++) {
                int nb = nt * 8;
                uint32_t b0 = Ws[k8 + tig][nb + gidl];
                uint32_t b1 = Ws[k8 + tig + 4][nb + gidl];
                mma_tf32(acc[nt], a, b0, b1);
            }
        }
        __syncthreads();
    }

    // Epilogue: store as half2 (one uint per (row, col pair)).
#pragma unroll
    for (int nt = 0; nt < 8; nt++) {
        int col = nt * 8 + 2 * tig;               // even
        int r0 = rowBase + warp_m + gidl;
        if (r0 < N)
            g_h2h[(size_t)r0 * 32 + (col >> 1)] = pack_half2(acc[nt][0], acc[nt][1]);
        if (r0 + 8 < N)
            g_h2h[(size_t)(r0 + 8) * 32 + (col >> 1)] = pack_half2(acc[nt][2], acc[nt][3]);
    }
}

// ---------------------------------------------------------------------------
// Layer-2 aggregation (CSR over half h2) + bias + fused warp log_softmax.
// All 32 lanes active: lane owns one half2 (2 of 64 cols). Unrolled x2.
// ---------------------------------------------------------------------------
__global__ void agg2_csr_kernel(const float* __restrict__ b2,
                                float* __restrict__ out, int N) {
    int gid = blockIdx.x * blockDim.x + threadIdx.x;
    int d = gid >> 5;
    int lane = gid & 31;
    if (d >= N) return;

    int end = g_off[d];
    int beg = end - g_cnt[d];

    float2 acc0 = make_float2(0.f, 0.f);
    float2 acc1 = make_float2(0.f, 0.f);
    int j = beg;
    for (; j + 1 < end; j += 2) {
        int2 p0 = g_epack[j], p1 = g_epack[j + 1];
        float w0 = __int_as_float(p0.y);
        float w1 = __int_as_float(p1.y);
        float2 v0 = unpack_half2(g_h2h[(size_t)p0.x * 32 + lane]);
        float2 v1 = unpack_half2(g_h2h[(size_t)p1.x * 32 + lane]);
        acc0.x = fmaf(v0.x, w0, acc0.x);
        acc0.y = fmaf(v0.y, w0, acc0.y);
        acc1.x = fmaf(v1.x, w1, acc1.x);
        acc1.y = fmaf(v1.y, w1, acc1.y);
    }
    if (j < end) {
        int2 p0 = g_epack[j];
        float w0 = __int_as_float(p0.y);
        float2 v0 = unpack_half2(g_h2h[(size_t)p0.x * 32 + lane]);
        acc0.x = fmaf(v0.x, w0, acc0.x);
        acc0.y = fmaf(v0.y, w0, acc0.y);
    }
    acc0.x += acc1.x; acc0.y += acc1.y;

    float dd = g_dinv[d];
    float dd2 = dd * dd;
    float2 hd = unpack_half2(g_h2h[(size_t)d * 32 + lane]);
    float2 bb = *(const float2*)(b2 + lane * 2);
    float2 o;
    o.x = fmaf(acc0.x, dd, fmaf(hd.x, dd2, bb.x));
    o.y = fmaf(acc0.y, dd, fmaf(hd.y, dd2, bb.y));

    float m = fmaxf(o.x, o.y);
#pragma unroll
    for (int off = 16; off > 0; off >>= 1)
        m = fmaxf(m, __shfl_xor_sync(0xFFFFFFFFu, m, off));
    float sum = expf(o.x - m) + expf(o.y - m);
#pragma unroll
    for (int off = 16; off > 0; off >>= 1)
        sum += __shfl_xor_sync(0xFFFFFFFFu, sum, off);
    float l = logf(sum) + m;
    *(float2*)(out + (size_t)d * COUT + lane * 2) =
        make_float2(o.x - l, o.y - l);
}

// ---------------------------------------------------------------------------
extern "C" void kernel_launch(void* const* d_in, const int* in_sizes, int n_in,
                              void* d_out, int out_size) {
    const float* x  = (const float*)d_in[0];
    const float* W1 = (const float*)d_in[1];
    const float* b1 = (const float*)d_in[2];
    const float* W2 = (const float*)d_in[3];
    const float* b2 = (const float*)d_in[4];
    const void*  ei = d_in[5];

    const int H   = in_sizes[2];                 // 128
    const int Fin = in_sizes[1] / H;             // 96
    const int C   = in_sizes[4];                 // 64
    const int N   = in_sizes[0] / Fin;           // 100000
    const int E   = in_sizes[5] / 2;             // 800000

    float* out = (float*)d_out;
    float* emb = ((long long)out_size >= (long long)N * (C + H))
                     ? out + (size_t)N * C
                     : nullptr;

    const int T = 256;
    const int nblk = (N + 255) / 256;

    // Init + dtype detect; convert x to half; convert+count edges.
    init_detect_kernel<<<(N + T - 1) / T, T>>>((const unsigned*)ei, E, N);
    x2h_kernel<<<(N * 24 + T - 1) / T, T>>>(x, N);
    idx_convert_count_kernel<<<(E + T - 1) / T, T>>>(ei, E);

    // CSR build: single fused scan (atomic block bases), then scatter.
    scan_fused_kernel<<<nblk, 256>>>(N);
    scatter_kernel<<<(E + T - 1) / T, T>>>(E);

    // Layer 1: aggregate half-x in input space (96-wide), then GEMM with
    // fused bias+relu+embedding epilogue.
    aggx_csr_kernel<<<(int)(((long long)N * 32 + T - 1) / T), T>>>(N);
    gemm1_tc_kernel<<<(N + 127) / 128, 256>>>(W1, b1, emb, N);

    // Layer 2: GEMM (half output) then aggregate (64-wide) with fused
    // bias + log_softmax.
    gemm2_tc_kernel<<<(N + 127) / 128, 256>>>(W2, N);
    agg2_csr_kernel<<<(int)(((long long)N * 32 + T - 1) / T), T>>>(b2, out, N);
}

// round 17
// speedup vs baseline: 1.0369x; 1.0369x over previous
#include <cuda_runtime.h>
#include <cuda_fp16.h>
#include <math.h>
#include <stdint.h>

// Problem shape (fixed by the dataset): N=100000, E=800000, F_IN=96, H=128, C=64.
#define MAXN 100000
#define MAXE 800000
#define FIN 96
#define HID 128
#define COUT 64

// Scratch (static __device__ — no allocations allowed in kernel_launch).
__device__ float4   g_dinv4[(MAXN + 3) / 4];            // d^{-1/2}
__device__ uint2    g_xh2[(size_t)MAXN * FIN / 4];      // x as half [N,96]
__device__ float4   g_aggx_4[(size_t)MAXN * FIN / 4];   // Â·x  (96-wide, fp32)
__device__ float4   g_h1b_4[(size_t)MAXN * HID / 4];    // relu(aggx@W1+b1)
__device__ uint32_t g_h2h[(size_t)MAXN * COUT / 2];     // h1b@W2 as half
__device__ int      g_cnt[MAXN];                        // in-degree (no self loop)
__device__ int      g_off[MAXN];                        // row base; after scatter: END
__device__ int2     g_epack[MAXE];                      // CSR slot: (src, dinv[src])
__device__ int      g_total;                            // fused-scan base counter
__device__ unsigned g_anyodd;

#define g_dinv ((float*)g_dinv4)
#define g_aggx ((float*)g_aggx_4)
#define g_h1b  ((float*)g_h1b_4)

// ---------------------------------------------------------------------------
// TF32 helpers
// ---------------------------------------------------------------------------
__device__ __forceinline__ uint32_t f2tf32(float f) {
    uint32_t r;
    asm("cvt.rna.tf32.f32 %0, %1;" : "=r"(r) : "f"(f));
    return r;
}

__device__ __forceinline__ void mma_tf32(float* d, const uint32_t* a,
                                         uint32_t b0, uint32_t b1) {
    asm volatile(
        "mma.sync.aligned.m16n8k8.row.col.f32.tf32.tf32.f32 "
        "{%0,%1,%2,%3}, {%4,%5,%6,%7}, {%8,%9}, {%0,%1,%2,%3};"
        : "+f"(d[0]), "+f"(d[1]), "+f"(d[2]), "+f"(d[3])
        : "r"(a[0]), "r"(a[1]), "r"(a[2]), "r"(a[3]), "r"(b0), "r"(b1));
}

__device__ __forceinline__ uint32_t pack_half2(float a, float b) {
    __half2 h = __floats2half2_rn(a, b);
    return *(uint32_t*)&h;
}

__device__ __forceinline__ float2 unpack_half2(uint32_t u) {
    return __half22float2(*(__half2*)&u);
}

// Fetch edge e's (src, dst) straight from the input buffer, either dtype.
// (R11 datum: direct read beats materializing g_src/g_dst by ~4us.)
__device__ __forceinline__ void load_edge(const void* ei, int E, int e,
                                          int& s, int& d) {
    if (g_anyodd) {                    // int32 layout
        const int* p = (const int*)ei;
        s = p[e]; d = p[E + e];
    } else {                           // int64 layout
        const long long* p = (const long long*)ei;
        s = (int)p[e]; d = (int)p[E + e];
    }
}

// ---------------------------------------------------------------------------
// Fused init: reset flags, zero degree counters, convert x -> half, and
// (block 1) probe the edge-index dtype. Grid covers N*24 uint2 conversions.
// int64 (LE, ids < 2^31): odd 32-bit words all 0; int32: odd words are real
// src ids (random in [0,N)) and cannot all be zero over 4096 samples.
// ---------------------------------------------------------------------------
__global__ void init_kernel(const float* __restrict__ x,
                            const unsigned* __restrict__ w, int E, int N) {
    int i = blockIdx.x * blockDim.x + threadIdx.x;
    if (i == 0) { g_anyodd = 0u; g_total = 0; }
    if (i < N) g_cnt[i] = 0;
    if (blockIdx.x == 1) {
        int limit = (E < 4096) ? E : 4096;
        unsigned acc = 0u;
        for (int t = threadIdx.x; t < limit; t += blockDim.x)
            acc |= w[2 * t + 1];
        for (int o = 16; o > 0; o >>= 1)
            acc |= __shfl_xor_sync(0xFFFFFFFFu, acc, o);
        if ((threadIdx.x & 31) == 0 && acc) atomicOr(&g_anyodd, acc);
    }
    if (i < N * 24) {                  // x fp32 -> half copy
        float4 v = ((const float4*)x)[i];
        uint2 o;
        o.x = pack_half2(v.x, v.y);
        o.y = pack_half2(v.z, v.w);
        g_xh2[i] = o;
    }
}

// Count in-degrees straight from the input buffer.
__global__ void count_kernel(const void* __restrict__ ei, int E) {
    int e = blockIdx.x * blockDim.x + threadIdx.x;
    if (e >= E) return;
    int s, d;
    load_edge(ei, E, e, s, d);
    atomicAdd(&g_cnt[d], 1);
}

// ---------------------------------------------------------------------------
// Fused single-pass "scan": per-block smem scan + one atomic base claim.
// CSR row order across nodes is irrelevant. Also computes dinv.
// ---------------------------------------------------------------------------
__global__ void scan_fused_kernel(int N) {
    __shared__ int sm[256];
    __shared__ int sbase;
    int i = blockIdx.x * 256 + threadIdx.x;
    int v = (i < N) ? g_cnt[i] : 0;
    sm[threadIdx.x] = v;
    __syncthreads();
#pragma unroll
    for (int o = 1; o < 256; o <<= 1) {
        int t = (threadIdx.x >= o) ? sm[threadIdx.x - o] : 0;
        __syncthreads();
        sm[threadIdx.x] += t;
        __syncthreads();
    }
    if (threadIdx.x == 255) sbase = atomicAdd(&g_total, sm[255]);
    __syncthreads();
    if (i < N) {
        g_off[i] = sbase + sm[threadIdx.x] - v;
        g_dinv[i] = rsqrtf((float)(v + 1));       // +1 = self loop
    }
}

// Scatter edges into CSR slots as packed (src, weight) int2, reading the
// edge buffer directly. atomicAdd on g_off: afterwards g_off[d] == row end.
__global__ void scatter_kernel(const void* __restrict__ ei, int E) {
    int e = blockIdx.x * blockDim.x + threadIdx.x;
    if (e >= E) return;
    int s, d;
    load_edge(ei, E, e, s, d);
    int pos = atomicAdd(&g_off[d], 1);
    g_epack[pos] = make_int2(s, __float_as_int(g_dinv[s]));
}

// ---------------------------------------------------------------------------
// Input-space aggregation (CSR, zero atomics): aggx = Â·x  (96-wide, half x).
// One warp per dst; lanes 0..23 each own 4 cols (one uint2 = 4 halves).
// Edge loop unrolled x2 (x4 regressed via L1tex-queue contention, R11/R12).
// ---------------------------------------------------------------------------
__global__ void aggx_csr_kernel(int N) {
    int gid = blockIdx.x * blockDim.x + threadIdx.x;
    int d = gid >> 5;
    int lane = gid & 31;
    if (d >= N || lane >= 24) return;

    int end = g_off[d];
    int beg = end - g_cnt[d];

    float4 acc0 = make_float4(0.f, 0.f, 0.f, 0.f);
    float4 acc1 = make_float4(0.f, 0.f, 0.f, 0.f);
    int j = beg;
    for (; j + 1 < end; j += 2) {
        int2 p0 = g_epack[j], p1 = g_epack[j + 1];
        float w0 = __int_as_float(p0.y);
        float w1 = __int_as_float(p1.y);
        uint2 u0 = g_xh2[(size_t)p0.x * 24 + lane];
        uint2 u1 = g_xh2[(size_t)p1.x * 24 + lane];
        float2 v0a = unpack_half2(u0.x), v0b = unpack_half2(u0.y);
        float2 v1a = unpack_half2(u1.x), v1b = unpack_half2(u1.y);
        acc0.x = fmaf(v0a.x, w0, acc0.x);
        acc0.y = fmaf(v0a.y, w0, acc0.y);
        acc0.z = fmaf(v0b.x, w0, acc0.z);
        acc0.w = fmaf(v0b.y, w0, acc0.w);
        acc1.x = fmaf(v1a.x, w1, acc1.x);
        acc1.y = fmaf(v1a.y, w1, acc1.y);
        acc1.z = fmaf(v1b.x, w1, acc1.z);
        acc1.w = fmaf(v1b.y, w1, acc1.w);
    }
    if (j < end) {
        int2 p0 = g_epack[j];
        float w0 = __int_as_float(p0.y);
        uint2 u0 = g_xh2[(size_t)p0.x * 24 + lane];
        float2 v0a = unpack_half2(u0.x), v0b = unpack_half2(u0.y);
        acc0.x = fmaf(v0a.x, w0, acc0.x);
        acc0.y = fmaf(v0a.y, w0, acc0.y);
        acc0.z = fmaf(v0b.x, w0, acc0.z);
        acc0.w = fmaf(v0b.y, w0, acc0.w);
    }
    acc0.x += acc1.x; acc0.y += acc1.y; acc0.z += acc1.z; acc0.w += acc1.w;

    float dd = g_dinv[d];
    float dd2 = dd * dd;
    uint2 ud = g_xh2[(size_t)d * 24 + lane];
    float2 xda = unpack_half2(ud.x), xdb = unpack_half2(ud.y);
    float4 r;
    r.x = fmaf(acc0.x, dd, xda.x * dd2);
    r.y = fmaf(acc0.y, dd, xda.y * dd2);
    r.z = fmaf(acc0.z, dd, xdb.x * dd2);
    r.w = fmaf(acc0.w, dd, xdb.y * dd2);
    g_aggx_4[(size_t)d * 24 + lane] = r;
}

// ---------------------------------------------------------------------------
// GEMM1 (TF32): h1b[N,128] = relu(aggx[N,96] @ W1[96,128] + b1); also emb.
// ---------------------------------------------------------------------------
__global__ void gemm1_tc_kernel(const float* __restrict__ W1,
                                const float* __restrict__ b1,
                                float* __restrict__ emb, int N) {
    __shared__ __align__(16) uint32_t Xs[128][36];
    __shared__ __align__(16) uint32_t Ws[32][132];
    const int tid = threadIdx.x;
    const int wid = tid >> 5;
    const int lane = tid & 31;
    const int gidl = lane >> 2;
    const int tig = lane & 3;
    const int warp_m = (wid >> 1) * 32;
    const int warp_n = (wid & 1) * 64;
    const int rowBase = blockIdx.x * 128;

    float acc[2][8][4];
#pragma unroll
    for (int mt = 0; mt < 2; mt++)
#pragma unroll
        for (int nt = 0; nt < 8; nt++)
#pragma unroll
            for (int i = 0; i < 4; i++) acc[mt][nt][i] = 0.0f;

    for (int k0 = 0; k0 < FIN; k0 += 32) {
#pragma unroll
        for (int t = tid; t < 1024; t += 256) {
            int r = t >> 3, c = (t & 7) * 4;
            int gr = rowBase + r;
            float4 v = make_float4(0.f, 0.f, 0.f, 0.f);
            if (gr < N) v = *(const float4*)(g_aggx + (size_t)gr * FIN + k0 + c);
            Xs[r][c + 0] = f2tf32(v.x);
            Xs[r][c + 1] = f2tf32(v.y);
            Xs[r][c + 2] = f2tf32(v.z);
            Xs[r][c + 3] = f2tf32(v.w);
        }
#pragma unroll
        for (int t = tid; t < 1024; t += 256) {
            int r = t >> 5, c = (t & 31) * 4;
            float4 v = *(const float4*)(W1 + (size_t)(k0 + r) * HID + c);
            Ws[r][c + 0] = f2tf32(v.x);
            Ws[r][c + 1] = f2tf32(v.y);
            Ws[r][c + 2] = f2tf32(v.z);
            Ws[r][c + 3] = f2tf32(v.w);
        }
        __syncthreads();

#pragma unroll
        for (int kk = 0; kk < 4; kk++) {
            int k8 = kk * 8;
            uint32_t a[2][4];
#pragma unroll
            for (int mt = 0; mt < 2; mt++) {
                int mb = warp_m + mt * 16;
                a[mt][0] = Xs[mb + gidl][k8 + tig];
                a[mt][1] = Xs[mb + gidl + 8][k8 + tig];
                a[mt][2] = Xs[mb + gidl][k8 + tig + 4];
                a[mt][3] = Xs[mb + gidl + 8][k8 + tig + 4];
            }
#pragma unroll
            for (int nt = 0; nt < 8; nt++) {
                int nb = warp_n + nt * 8;
                uint32_t b0 = Ws[k8 + tig][nb + gidl];
                uint32_t b1v = Ws[k8 + tig + 4][nb + gidl];
                mma_tf32(acc[0][nt], a[0], b0, b1v);
                mma_tf32(acc[1][nt], a[1], b0, b1v);
            }
        }
        __syncthreads();
    }

#pragma unroll
    for (int mt = 0; mt < 2; mt++) {
#pragma unroll
        for (int nt = 0; nt < 8; nt++) {
            int col = warp_n + nt * 8 + 2 * tig;
            float2 bb = *(const float2*)(b1 + col);
            int r0 = rowBase + warp_m + mt * 16 + gidl;
            if (r0 < N) {
                float2 v = make_float2(fmaxf(acc[mt][nt][0] + bb.x, 0.f),
                                       fmaxf(acc[mt][nt][1] + bb.y, 0.f));
                *(float2*)(g_h1b + (size_t)r0 * HID + col) = v;
                if (emb) *(float2*)(emb + (size_t)r0 * HID + col) = v;
            }
            if (r0 + 8 < N) {
                float2 v = make_float2(fmaxf(acc[mt][nt][2] + bb.x, 0.f),
                                       fmaxf(acc[mt][nt][3] + bb.y, 0.f));
                *(float2*)(g_h1b + (size_t)(r0 + 8) * HID + col) = v;
                if (emb) *(float2*)(emb + (size_t)(r0 + 8) * HID + col) = v;
            }
        }
    }
}

// ---------------------------------------------------------------------------
// GEMM2 (TF32): h2[N,64] = g_h1b[N,128] @ W2[128,64], stored as HALF.
// ---------------------------------------------------------------------------
__global__ void gemm2_tc_kernel(const float* __restrict__ W2, int N) {
    __shared__ __align__(16) uint32_t Xs[128][36];
    __shared__ __align__(16) uint32_t Ws[32][68];
    const int tid = threadIdx.x;
    const int wid = tid >> 5;
    const int lane = tid & 31;
    const int gidl = lane >> 2;
    const int tig = lane & 3;
    const int warp_m = wid * 16;
    const int rowBase = blockIdx.x * 128;

    float acc[8][4];
#pragma unroll
    for (int nt = 0; nt < 8; nt++)
#pragma unroll
        for (int i = 0; i < 4; i++) acc[nt][i] = 0.0f;

    for (int k0 = 0; k0 < HID; k0 += 32) {
#pragma unroll
        for (int t = tid; t < 1024; t += 256) {
            int r = t >> 3, c = (t & 7) * 4;
            int gr = rowBase + r;
            float4 v = make_float4(0.f, 0.f, 0.f, 0.f);
            if (gr < N) v = *(const float4*)(g_h1b + (size_t)gr * HID + k0 + c);
            Xs[r][c + 0] = f2tf32(v.x);
            Xs[r][c + 1] = f2tf32(v.y);
            Xs[r][c + 2] = f2tf32(v.z);
            Xs[r][c + 3] = f2tf32(v.w);
        }
#pragma unroll
        for (int t = tid; t < 512; t += 256) {
            int r = t >> 4, c = (t & 15) * 4;
            float4 v = *(const float4*)(W2 + (size_t)(k0 + r) * COUT + c);
            Ws[r][c + 0] = f2tf32(v.x);
            Ws[r][c + 1] = f2tf32(v.y);
            Ws[r][c + 2] = f2tf32(v.z);
            Ws[r][c + 3] = f2tf32(v.w);
        }
        __syncthreads();

#pragma unroll
        for (int kk = 0; kk < 4; kk++) {
            int k8 = kk * 8;
            uint32_t a[4];
            a[0] = Xs[warp_m + gidl][k8 + tig];
            a[1] = Xs[warp_m + gidl + 8][k8 + tig];
            a[2] = Xs[warp_m + gidl][k8 + tig + 4];
            a[3] = Xs[warp_m + gidl + 8][k8 + tig + 4];
#pragma unroll
            for (int nt = 0; nt < 8; nt++) {
                int nb = nt * 8;
                uint32_t b0 = Ws[k8 + tig][nb + gidl];
                uint32_t b1 = Ws[k8 + tig + 4][nb + gidl];
                mma_tf32(acc[nt], a, b0, b1);
            }
        }
        __syncthreads();
    }

#pragma unroll
    for (int nt = 0; nt < 8; nt++) {
        int col = nt * 8 + 2 * tig;
        int r0 = rowBase + warp_m + gidl;
        if (r0 < N)
            g_h2h[(size_t)r0 * 32 + (col >> 1)] = pack_half2(acc[nt][0], acc[nt][1]);
        if (r0 + 8 < N)
            g_h2h[(size_t)(r0 + 8) * 32 + (col >> 1)] = pack_half2(acc[nt][2], acc[nt][3]);
    }
}

// ---------------------------------------------------------------------------
// Layer-2 aggregation (CSR over half h2) + bias + fused warp log_softmax.
// All 32 lanes active: lane owns one half2 (2 of 64 cols). Unrolled x2.
// ---------------------------------------------------------------------------
__global__ void agg2_csr_kernel(const float* __restrict__ b2,
                                float* __restrict__ out, int N) {
    int gid = blockIdx.x * blockDim.x + threadIdx.x;
    int d = gid >> 5;
    int lane = gid & 31;
    if (d >= N) return;

    int end = g_off[d];
    int beg = end - g_cnt[d];

    float2 acc0 = make_float2(0.f, 0.f);
    float2 acc1 = make_float2(0.f, 0.f);
    int j = beg;
    for (; j + 1 < end; j += 2) {
        int2 p0 = g_epack[j], p1 = g_epack[j + 1];
        float w0 = __int_as_float(p0.y);
        float w1 = __int_as_float(p1.y);
        float2 v0 = unpack_half2(g_h2h[(size_t)p0.x * 32 + lane]);
        float2 v1 = unpack_half2(g_h2h[(size_t)p1.x * 32 + lane]);
        acc0.x = fmaf(v0.x, w0, acc0.x);
        acc0.y = fmaf(v0.y, w0, acc0.y);
        acc1.x = fmaf(v1.x, w1, acc1.x);
        acc1.y = fmaf(v1.y, w1, acc1.y);
    }
    if (j < end) {
        int2 p0 = g_epack[j];
        float w0 = __int_as_float(p0.y);
        float2 v0 = unpack_half2(g_h2h[(size_t)p0.x * 32 + lane]);
        acc0.x = fmaf(v0.x, w0, acc0.x);
        acc0.y = fmaf(v0.y, w0, acc0.y);
    }
    acc0.x += acc1.x; acc0.y += acc1.y;

    float dd = g_dinv[d];
    float dd2 = dd * dd;
    float2 hd = unpack_half2(g_h2h[(size_t)d * 32 + lane]);
    float2 bb = *(const float2*)(b2 + lane * 2);
    float2 o;
    o.x = fmaf(acc0.x, dd, fmaf(hd.x, dd2, bb.x));
    o.y = fmaf(acc0.y, dd, fmaf(hd.y, dd2, bb.y));

    float m = fmaxf(o.x, o.y);
#pragma unroll
    for (int off = 16; off > 0; off >>= 1)
        m = fmaxf(m, __shfl_xor_sync(0xFFFFFFFFu, m, off));
    float sum = expf(o.x - m) + expf(o.y - m);
#pragma unroll
    for (int off = 16; off > 0; off >>= 1)
        sum += __shfl_xor_sync(0xFFFFFFFFu, sum, off);
    float l = logf(sum) + m;
    *(float2*)(out + (size_t)d * COUT + lane * 2) =
        make_float2(o.x - l, o.y - l);
}

// ---------------------------------------------------------------------------
extern "C" void kernel_launch(void* const* d_in, const int* in_sizes, int n_in,
                              void* d_out, int out_size) {
    const float* x  = (const float*)d_in[0];
    const float* W1 = (const float*)d_in[1];
    const float* b1 = (const float*)d_in[2];
    const float* W2 = (const float*)d_in[3];
    const float* b2 = (const float*)d_in[4];
    const void*  ei = d_in[5];

    const int H   = in_sizes[2];                 // 128
    const int Fin = in_sizes[1] / H;             // 96
    const int C   = in_sizes[4];                 // 64
    const int N   = in_sizes[0] / Fin;           // 100000
    const int E   = in_sizes[5] / 2;             // 800000

    float* out = (float*)d_out;
    float* emb = ((long long)out_size >= (long long)N * (C + H))
                     ? out + (size_t)N * C
                     : nullptr;

    const int T = 256;
    const int nblk = (N + 255) / 256;

    // Fused init (reset + cnt zero + x->half + dtype probe), then count.
    init_kernel<<<(N * 24 + T - 1) / T, T>>>(x, (const unsigned*)ei, E, N);
    count_kernel<<<(E + T - 1) / T, T>>>(ei, E);

    // CSR build: single fused scan (atomic block bases), then direct-read scatter.
    scan_fused_kernel<<<nblk, 256>>>(N);
    scatter_kernel<<<(E + T - 1) / T, T>>>(ei, E);

    // Layer 1: aggregate half-x in input space (96-wide), then GEMM with
    // fused bias+relu+embedding epilogue.
    aggx_csr_kernel<<<(int)(((long long)N * 32 + T - 1) / T), T>>>(N);
    gemm1_tc_kernel<<<(N + 127) / 128, 256>>>(W1, b1, emb, N);

    // Layer 2: GEMM (half output) then aggregate (64-wide) with fused
    // bias + log_softmax.
    gemm2_tc_kernel<<<(N + 127) / 128, 256>>>(W2, N);
    agg2_csr_kernel<<<(int)(((long long)N * 32 + T - 1) / T), T>>>(b2, out, N);
}